// round 16
// baseline (speedup 1.0000x reference)
#include <cuda_runtime.h>
#include <cstdint>
#include <math.h>

// Problem dims (fixed)
#define Bb 128
#define Tt 512
#define Hh 1024
#define BT (Bb*Tt)

// -------- device-global scratch ------------------------------------------
__device__ float g_eproj[1024 * 1024];     // embed @ Wx^T + (bx+bh)  (4 MB, L2-resident)
__device__ float g_h[2][Bb * Hh];          // h double buffer (rounded+permuted)
__device__ float g_embr[1024 * 1024];      // rounded+permuted embed table
__device__ float g_Wxr[1024 * 1024];       // rounded+permuted Wx
__device__ float g_Wor[1024 * 1024];       // rounded+permuted Wo (L2-resident in rnn)
__device__ float g_bsum[1024];             // bx + bh (fused step bias)
__device__ unsigned int g_flag[128 * 32];  // per-CTA publish counters, 128B apart

// -------- helpers --------------------------------------------------------
__device__ __forceinline__ uint32_t f2t(float x) {
    uint32_t u; asm("cvt.rna.tf32.f32 %0, %1;" : "=r"(u) : "f"(x));
    return u;
}
__device__ __forceinline__ float rndt(float x) { return __uint_as_float(f2t(x)); }
// k-pair interleave within 8-blocks: (j, j+4) -> positions (2j, 2j+1)
__device__ __forceinline__ int pig(int k) {
    int j = k & 7;
    return (k & ~7) | ((j < 4) ? (2 * j) : (2 * (j - 4) + 1));
}
__device__ __forceinline__ void cp16(float* s, const float* g) {
    uint32_t sa = (uint32_t)__cvta_generic_to_shared(s);
    asm volatile("cp.async.cg.shared.global [%0], [%1], 16;\n" :: "r"(sa), "l"(g));
}
__device__ __forceinline__ void cp_commit() { asm volatile("cp.async.commit_group;\n"); }
template<int N> __device__ __forceinline__ void cp_wait() {
    asm volatile("cp.async.wait_group %0;\n" :: "n"(N));
}
__device__ __forceinline__ void mma8(float* c, const uint32_t* a, const uint32_t* b) {
    asm volatile(
        "mma.sync.aligned.m16n8k8.row.col.f32.tf32.tf32.f32 "
        "{%0,%1,%2,%3},{%4,%5,%6,%7},{%8,%9},{%0,%1,%2,%3};"
        : "+f"(c[0]), "+f"(c[1]), "+f"(c[2]), "+f"(c[3])
        : "r"(a[0]), "r"(a[1]), "r"(a[2]), "r"(a[3]), "r"(b[0]), "r"(b[1]));
}
// fast tanh: 1 - 2/(exp(2x)+1) via ex2/rcp approx (saturates to +-1 at inf)
__device__ __forceinline__ float ftanh(float x) {
    float e;
    asm("ex2.approx.ftz.f32 %0, %1;" : "=f"(e) : "f"(x * 2.885390081777927f));
    float rc;
    asm("rcp.approx.ftz.f32 %0, %1;" : "=f"(rc) : "f"(e + 1.0f));
    return fmaf(-2.0f, rc, 1.0f);
}

// -------- prologue: round+permute embed, Wx, Wo --------------------------
__global__ void prep_k(const float* __restrict__ e, const float* __restrict__ wx,
                       const float* __restrict__ wo) {
    int st = gridDim.x * blockDim.x;
    for (int i = blockIdx.x * blockDim.x + threadIdx.x; i < 1024 * 1024; i += st) {
        int r = i >> 10, k = i & 1023;
        int d = (r << 10) | pig(k);
        g_embr[d] = rndt(e[i]);
        g_Wxr[d]  = rndt(wx[i]);
        g_Wor[d]  = rndt(wo[i]);
    }
}

__global__ void init_k(const float* __restrict__ h0, const float* __restrict__ bx,
                       const float* __restrict__ bh) {
    int i = blockIdx.x * blockDim.x + threadIdx.x;
    if (i < 128) g_flag[i * 32] = 0u;
    if (i < 1024) g_bsum[i] = bx[i] + bh[i];
    for (int j = i; j < Bb * Hh; j += gridDim.x * blockDim.x) {
        int r = j >> 10, k = j & 1023;
        g_h[0][(r << 10) | pig(k)] = rndt(h0[j]);
    }
}

// -------- phase GEMM (eproj only): C = A @ W^T + bias --------------------
#define PS 44
#define TSZ 5632

__device__ __forceinline__ void stage_p(const float* const* rp, const float* __restrict__ W,
                                        int n0, int k0, float* As, float* Bs, int tid) {
    #pragma unroll
    for (int j = 0; j < 4; j++) {
        int c = j * 256 + tid; int r = c >> 3, o = c & 7;
        cp16(As + r * PS + o * 4, rp[r] + k0 + o * 4);
    }
    #pragma unroll
    for (int j = 0; j < 4; j++) {
        int c = j * 256 + tid; int r = c >> 3, o = c & 7;
        cp16(Bs + r * PS + o * 4, W + (size_t)(n0 + r) * 1024 + k0 + o * 4);
    }
}

__global__ __launch_bounds__(256, 2) void gemm_k(const float* __restrict__ Ab,
                                                 const float* __restrict__ W,
                                                 const float* __restrict__ bias,
                                                 float* __restrict__ C) {
    extern __shared__ float sm[];
    float* As = sm;
    float* Bs = sm + 2 * TSZ;
    const float** rp = (const float**)(sm + 4 * TSZ);

    const int tid = threadIdx.x;
    if (tid < 128) rp[tid] = Ab + ((size_t)blockIdx.y * 128 + tid) * 1024;
    __syncthreads();

    const int n0 = blockIdx.x * 128;
    const int lane = tid & 31, w = tid >> 5;
    const int g = lane >> 2, t4 = lane & 3;
    const int wm = (w >> 2) * 64, wn = (w & 3) * 32;

    float acc[4][4][4];
    #pragma unroll
    for (int a = 0; a < 4; a++)
        #pragma unroll
        for (int b = 0; b < 4; b++)
            #pragma unroll
            for (int c = 0; c < 4; c++) acc[a][b][c] = 0.f;

    stage_p(rp, W, n0, 0, As, Bs, tid);
    cp_commit();

    for (int ks = 0; ks < 32; ks++) {
        cp_wait<0>();
        __syncthreads();
        if (ks < 31) {
            int nb2 = (ks + 1) & 1;
            stage_p(rp, W, n0, (ks + 1) * 32, As + nb2 * TSZ, Bs + nb2 * TSZ, tid);
            cp_commit();
        }
        const float* A_ = As + (ks & 1) * TSZ;
        const float* B_ = Bs + (ks & 1) * TSZ;
        #pragma unroll
        for (int kk = 0; kk < 32; kk += 8) {
            uint32_t a[4][4];
            #pragma unroll
            for (int mi = 0; mi < 4; mi++) {
                float2 p0 = *(const float2*)&A_[(wm + mi * 16 + g) * PS + kk + 2 * t4];
                float2 p1 = *(const float2*)&A_[(wm + mi * 16 + 8 + g) * PS + kk + 2 * t4];
                a[mi][0] = __float_as_uint(p0.x); a[mi][1] = __float_as_uint(p1.x);
                a[mi][2] = __float_as_uint(p0.y); a[mi][3] = __float_as_uint(p1.y);
            }
            #pragma unroll
            for (int ni = 0; ni < 4; ni++) {
                float2 q = *(const float2*)&B_[(wn + ni * 8 + g) * PS + kk + 2 * t4];
                uint32_t b[2] = { __float_as_uint(q.x), __float_as_uint(q.y) };
                #pragma unroll
                for (int mi = 0; mi < 4; mi++)
                    mma8(acc[mi][ni], a[mi], b);
            }
        }
    }

    const int m0 = blockIdx.y * 128;
    #pragma unroll
    for (int ni = 0; ni < 4; ni++) {
        int nc = n0 + wn + ni * 8 + 2 * t4;
        float b0 = bias[nc], b1 = bias[nc + 1];
        #pragma unroll
        for (int mi = 0; mi < 4; mi++) {
            int r0 = m0 + wm + mi * 16 + g;
            *(float2*)&C[(size_t)r0 * 1024 + nc] =
                make_float2(acc[mi][ni][0] + b0, acc[mi][ni][1] + b1);
            *(float2*)&C[(size_t)(r0 + 8) * 1024 + nc] =
                make_float2(acc[mi][ni][2] + b0, acc[mi][ni][3] + b1);
        }
    }
}

// -------- fused recurrence + output kernel --------------------------------
// 128 CTAs = 4 M-groups x 32 N-CTAs, 256 thr (8 warps).
// Per iter t (0..Tt inclusive):
//   poll producers, stage full h(t-1)[mb:mb+32, :] (4 chunks/warp)
//   t<Tt: h-GEMM (Wh in regs) -> h partials -> Pa; reducers: tanh/hd/release
//   t>0 : y-GEMM (same staged h, Wo frags streamed from L2) in the handoff
//         shadow -> y partials -> Pa -> reduce + bo -> y_e(t-1)
#define STG 36
#define CHB (32 * STG)      // 1152 floats per chunk buffer
#define CHW (4 * CHB)       // per-warp staging: 4608 floats
#define PA_O (8 * CHW)      // partials area: 8 x 32 x 36 floats
#define SMEM_RF (PA_O + 8 * CHB)   // 46080 floats = 184320 B

__global__ __launch_bounds__(256, 1) void rnn_k(const float* __restrict__ Wh,
                                                const int* __restrict__ xtok,
                                                const float* __restrict__ bo,
                                                float* __restrict__ h_e,
                                                float* __restrict__ y_e) {
    extern __shared__ float sm[];
    float* Stg = sm;                       // 8 warps x 4 x (32x36)
    float* Pa  = sm + PA_O;                // partials (h then y, per iteration)

    const int tid = threadIdx.x;
    const int nq = blockIdx.x & 31, mq = blockIdx.x >> 5;
    const int nb = nq * 32, mb = mq * 32;

    const int lane = tid & 31, w = tid >> 5;
    const int g = lane >> 2, t4 = lane & 3;
    const int kb = w * 128;
    float* SB = Stg + w * CHW;
    const int srow = lane >> 3, su = lane & 7;

    unsigned int* pflag = &g_flag[((mq << 5) | (4 * w + (lane & 3))) * 32];
    unsigned int* myflag = &g_flag[blockIdx.x * 32];

    // Wh B-fragments in registers (rounded RNA; once)
    uint32_t bfr[4][16][2];
    #pragma unroll
    for (int ni = 0; ni < 4; ni++) {
        const float* Wrow = Wh + (size_t)(nb + ni * 8 + g) * 1024 + kb + t4;
        #pragma unroll
        for (int kf = 0; kf < 16; kf++) {
            bfr[ni][kf][0] = f2t(Wrow[kf * 8]);
            bfr[ni][kf][1] = f2t(Wrow[kf * 8 + 4]);
        }
    }
    // Wo fragment base pointers (rounded+permuted table, L2-resident)
    const float* worow[4];
    #pragma unroll
    for (int ni = 0; ni < 4; ni++)
        worow[ni] = g_Wor + (size_t)(nb + ni * 8 + g) * 1024 + kb + 2 * t4;

    // epilogue mapping (tid<128): row er, cols [gcb, gcb+8)
    const int er = tid & 31, eblk = tid >> 5;
    const int gr = mb + er, gcb = nb + eblk * 8;
    float4 xq0, xq1, bov0, bov1;
    if (tid < 128) {
        int tk = xtok[gr * Tt];
        xq0 = *(const float4*)&g_eproj[(size_t)tk * 1024 + gcb];
        xq1 = *(const float4*)&g_eproj[(size_t)tk * 1024 + gcb + 4];
        bov0 = *(const float4*)&bo[gcb];
        bov1 = *(const float4*)&bo[gcb + 4];
    }
    __syncthreads();

    for (int t = 0; t <= Tt; t++) {
        const float* hs = g_h[t & 1];
        float* hd = g_h[(t + 1) & 1];
        const float* gsrc = hs + (size_t)mb * 1024 + kb;

        // acquire producers (flag >= t means h(t-1) published)
        if (t > 0 && lane < 4) {
            unsigned tgt = (unsigned)t, vv;
            do {
                asm volatile("ld.acquire.gpu.u32 %0, [%1];" : "=r"(vv) : "l"(pflag));
            } while (vv < tgt);
        }
        __syncwarp();

        // stage all 4 chunks (one L2 round trip)
        #pragma unroll
        for (int cc = 0; cc < 4; cc++) {
            #pragma unroll
            for (int j = 0; j < 8; j++) {
                int r = srow + 4 * j;
                cp16(SB + cc * CHB + r * STG + su * 4,
                     gsrc + (size_t)r * 1024 + cc * 32 + su * 4);
            }
            cp_commit();
        }

        float acc[2][4][4];
        if (t < Tt) {
            // ---- h-GEMM ----
            #pragma unroll
            for (int a = 0; a < 2; a++)
                #pragma unroll
                for (int b = 0; b < 4; b++)
                    #pragma unroll
                    for (int c = 0; c < 4; c++) acc[a][b][c] = 0.f;
            #pragma unroll
            for (int c = 0; c < 4; c++) {
                if (c == 0) cp_wait<3>();
                else if (c == 1) cp_wait<2>();
                else if (c == 2) cp_wait<1>();
                else cp_wait<0>();
                __syncwarp();
                const float* B_ = SB + c * CHB;
                #pragma unroll
                for (int kf = 0; kf < 4; kf++) {
                    uint32_t a[2][4];
                    #pragma unroll
                    for (int mi = 0; mi < 2; mi++) {
                        float2 p0 = *(const float2*)&B_[(mi * 16 + g) * STG + kf * 8 + 2 * t4];
                        float2 p1 = *(const float2*)&B_[(mi * 16 + 8 + g) * STG + kf * 8 + 2 * t4];
                        a[mi][0] = __float_as_uint(p0.x); a[mi][1] = __float_as_uint(p1.x);
                        a[mi][2] = __float_as_uint(p0.y); a[mi][3] = __float_as_uint(p1.y);
                    }
                    #pragma unroll
                    for (int ni = 0; ni < 4; ni++) {
                        mma8(acc[0][ni], a[0], bfr[ni][c * 4 + kf]);
                        mma8(acc[1][ni], a[1], bfr[ni][c * 4 + kf]);
                    }
                }
            }
            // h partials -> Pa
            float* Redw = Pa + w * CHB;
            #pragma unroll
            for (int mi = 0; mi < 2; mi++)
                #pragma unroll
                for (int ni = 0; ni < 4; ni++) {
                    int nc = ni * 8 + 2 * t4;
                    *(float2*)&Redw[(mi * 16 + g) * STG + nc] =
                        make_float2(acc[mi][ni][0], acc[mi][ni][1]);
                    *(float2*)&Redw[(mi * 16 + 8 + g) * STG + nc] =
                        make_float2(acc[mi][ni][2], acc[mi][ni][3]);
                }
        } else {
            cp_wait<0>();
            __syncwarp();
        }
        __syncthreads();   // (A) h partials visible; staging complete

        // ---- reducers: h epilogue (early release) ----
        if (t < Tt && tid < 128) {
            float s[8] = {0.f,0.f,0.f,0.f,0.f,0.f,0.f,0.f};
            #pragma unroll
            for (int ww = 0; ww < 8; ww++) {
                const float* Rr = Pa + ww * CHB + er * STG + eblk * 8;
                float4 r0 = *(const float4*)&Rr[0];
                float4 r1 = *(const float4*)&Rr[4];
                s[0] += r0.x; s[1] += r0.y; s[2] += r0.z; s[3] += r0.w;
                s[4] += r1.x; s[5] += r1.y; s[6] += r1.z; s[7] += r1.w;
            }
            float v[8], r[8];
            v[0] = ftanh(s[0] + xq0.x); v[1] = ftanh(s[1] + xq0.y);
            v[2] = ftanh(s[2] + xq0.z); v[3] = ftanh(s[3] + xq0.w);
            v[4] = ftanh(s[4] + xq1.x); v[5] = ftanh(s[5] + xq1.y);
            v[6] = ftanh(s[6] + xq1.z); v[7] = ftanh(s[7] + xq1.w);
            #pragma unroll
            for (int j = 0; j < 8; j++) r[j] = rndt(v[j]);
            *(float4*)&hd[(size_t)gr * 1024 + gcb]     = make_float4(r[0], r[4], r[1], r[5]);
            *(float4*)&hd[(size_t)gr * 1024 + gcb + 4] = make_float4(r[2], r[6], r[3], r[7]);

            asm volatile("bar.sync 1, 128;" ::: "memory");
            if (tid == 0)
                asm volatile("red.release.gpu.global.add.u32 [%0], %1;"
                             :: "l"(myflag), "r"(1u) : "memory");

            size_t orow = ((size_t)gr * Tt + t) * 1024 + gcb;
            *(float4*)&h_e[orow]     = make_float4(v[0], v[1], v[2], v[3]);
            *(float4*)&h_e[orow + 4] = make_float4(v[4], v[5], v[6], v[7]);
        }

        // ---- y-GEMM for step t-1 (same staged h; Wo frags from L2) ----
        if (t > 0) {
            #pragma unroll
            for (int a = 0; a < 2; a++)
                #pragma unroll
                for (int b = 0; b < 4; b++)
                    #pragma unroll
                    for (int c = 0; c < 4; c++) acc[a][b][c] = 0.f;
            #pragma unroll
            for (int c = 0; c < 4; c++) {
                const float* B_ = SB + c * CHB;
                #pragma unroll
                for (int kf = 0; kf < 4; kf++) {
                    uint32_t a[2][4];
                    #pragma unroll
                    for (int mi = 0; mi < 2; mi++) {
                        float2 p0 = *(const float2*)&B_[(mi * 16 + g) * STG + kf * 8 + 2 * t4];
                        float2 p1 = *(const float2*)&B_[(mi * 16 + 8 + g) * STG + kf * 8 + 2 * t4];
                        a[mi][0] = __float_as_uint(p0.x); a[mi][1] = __float_as_uint(p1.x);
                        a[mi][2] = __float_as_uint(p0.y); a[mi][3] = __float_as_uint(p1.y);
                    }
                    #pragma unroll
                    for (int ni = 0; ni < 4; ni++) {
                        float2 q = __ldg((const float2*)(worow[ni] + (c * 4 + kf) * 8));
                        uint32_t b[2] = { __float_as_uint(q.x), __float_as_uint(q.y) };
                        mma8(acc[0][ni], a[0], b);
                        mma8(acc[1][ni], a[1], b);
                    }
                }
            }
        }
        __syncthreads();   // (B) h-partial reads done; y accs ready

        if (t > 0) {
            float* Redw = Pa + w * CHB;
            #pragma unroll
            for (int mi = 0; mi < 2; mi++)
                #pragma unroll
                for (int ni = 0; ni < 4; ni++) {
                    int nc = ni * 8 + 2 * t4;
                    *(float2*)&Redw[(mi * 16 + g) * STG + nc] =
                        make_float2(acc[mi][ni][0], acc[mi][ni][1]);
                    *(float2*)&Redw[(mi * 16 + 8 + g) * STG + nc] =
                        make_float2(acc[mi][ni][2], acc[mi][ni][3]);
                }
        }
        __syncthreads();   // (C) y partials visible

        if (tid < 128) {
            if (t > 0) {
                float s[8] = {0.f,0.f,0.f,0.f,0.f,0.f,0.f,0.f};
                #pragma unroll
                for (int ww = 0; ww < 8; ww++) {
                    const float* Rr = Pa + ww * CHB + er * STG + eblk * 8;
                    float4 r0 = *(const float4*)&Rr[0];
                    float4 r1 = *(const float4*)&Rr[4];
                    s[0] += r0.x; s[1] += r0.y; s[2] += r0.z; s[3] += r0.w;
                    s[4] += r1.x; s[5] += r1.y; s[6] += r1.z; s[7] += r1.w;
                }
                size_t yrow = ((size_t)gr * Tt + (t - 1)) * 1024 + gcb;
                *(float4*)&y_e[yrow] =
                    make_float4(s[0] + bov0.x, s[1] + bov0.y, s[2] + bov0.z, s[3] + bov0.w);
                *(float4*)&y_e[yrow + 4] =
                    make_float4(s[4] + bov1.x, s[5] + bov1.y, s[6] + bov1.z, s[7] + bov1.w);
            }
            if (t + 1 < Tt) {
                int tk = xtok[gr * Tt + t + 1];
                xq0 = *(const float4*)&g_eproj[(size_t)tk * 1024 + gcb];
                xq1 = *(const float4*)&g_eproj[(size_t)tk * 1024 + gcb + 4];
            }
        }
        __syncthreads();   // (D) y-partial reads done -> buffers reusable
    }
}

// -------- launch ---------------------------------------------------------
extern "C" void kernel_launch(void* const* d_in, const int* in_sizes, int n_in,
                              void* d_out, int out_size) {
    (void)in_sizes; (void)n_in; (void)out_size;
    const int*   x      = (const int*)d_in[0];
    const float* h_init = (const float*)d_in[1];
    const float* embed  = (const float*)d_in[2];
    const float* Wx     = (const float*)d_in[3];
    const float* bx     = (const float*)d_in[4];
    const float* Wh     = (const float*)d_in[5];
    const float* bh     = (const float*)d_in[6];
    const float* Wo     = (const float*)d_in[7];
    const float* bo     = (const float*)d_in[8];

    float* out = (float*)d_out;
    float* h_e = out;                       // [B][T][H]
    float* y_e = out + (size_t)BT * Hh;     // [B][T][V]

    const int SMEM_P = 4 * TSZ * 4 + 128 * 8;               // 91136
    const int SMEM_R = SMEM_RF * 4;                         // 184320

    cudaFuncSetAttribute(gemm_k, cudaFuncAttributeMaxDynamicSharedMemorySize, SMEM_P);
    cudaFuncSetAttribute(rnn_k,  cudaFuncAttributeMaxDynamicSharedMemorySize, SMEM_R);

    void* ep_ptr = nullptr;   cudaGetSymbolAddress(&ep_ptr, g_eproj);
    void* emb_ptr = nullptr;  cudaGetSymbolAddress(&emb_ptr, g_embr);
    void* wx_ptr = nullptr;   cudaGetSymbolAddress(&wx_ptr, g_Wxr);
    void* bs_ptr = nullptr;   cudaGetSymbolAddress(&bs_ptr, g_bsum);

    // 1. round+permute embed/Wx/Wo; reset flags; bx+bh; h_init -> g_h[0]
    prep_k<<<512, 256>>>(embed, Wx, Wo);
    init_k<<<128, 256>>>(h_init, bx, bh);
    // 2. eproj = embed_r @ Wx_r^T + (bx+bh)   [1024x1024 — gather commutes]
    gemm_k<<<dim3(8, 8), 256, SMEM_P>>>((const float*)emb_ptr,
                                        (const float*)wx_ptr, (const float*)bs_ptr,
                                        (float*)ep_ptr);
    // 3. fused recurrence + output projection -> h_e, y_e
    rnn_k<<<128, 256, SMEM_R>>>(Wh, x, bo, h_e, y_e);
}

// round 17
// speedup vs baseline: 1.0253x; 1.0253x over previous
#include <cuda_runtime.h>
#include <cstdint>
#include <math.h>

// Problem dims (fixed)
#define Bb 128
#define Tt 512
#define Hh 1024
#define BT (Bb*Tt)

// -------- device-global scratch ------------------------------------------
__device__ float g_eproj[1024 * 1024];     // embed @ Wx^T + (bx+bh)  (4 MB, L2-resident)
__device__ float g_h[2][Bb * Hh];          // h double buffer (rounded+permuted)
__device__ float g_embr[1024 * 1024];      // rounded+permuted embed table
__device__ float g_Wxr[1024 * 1024];       // rounded+permuted Wx
__device__ float g_Wor[1024 * 1024];       // rounded+permuted Wo (L2-resident in rnn)
__device__ float g_bsum[1024];             // bx + bh (fused step bias)
__device__ unsigned int g_flag[128 * 32];  // per-CTA publish counters, 128B apart

// -------- helpers --------------------------------------------------------
__device__ __forceinline__ uint32_t f2t(float x) {
    uint32_t u; asm("cvt.rna.tf32.f32 %0, %1;" : "=r"(u) : "f"(x));
    return u;
}
__device__ __forceinline__ float rndt(float x) { return __uint_as_float(f2t(x)); }
// k-pair interleave within 8-blocks: (j, j+4) -> positions (2j, 2j+1)
__device__ __forceinline__ int pig(int k) {
    int j = k & 7;
    return (k & ~7) | ((j < 4) ? (2 * j) : (2 * (j - 4) + 1));
}
__device__ __forceinline__ void cp16(float* s, const float* g) {
    uint32_t sa = (uint32_t)__cvta_generic_to_shared(s);
    asm volatile("cp.async.cg.shared.global [%0], [%1], 16;\n" :: "r"(sa), "l"(g));
}
__device__ __forceinline__ void cp_commit() { asm volatile("cp.async.commit_group;\n"); }
template<int N> __device__ __forceinline__ void cp_wait() {
    asm volatile("cp.async.wait_group %0;\n" :: "n"(N));
}
__device__ __forceinline__ void mma8(float* c, const uint32_t* a, const uint32_t* b) {
    asm volatile(
        "mma.sync.aligned.m16n8k8.row.col.f32.tf32.tf32.f32 "
        "{%0,%1,%2,%3},{%4,%5,%6,%7},{%8,%9},{%0,%1,%2,%3};"
        : "+f"(c[0]), "+f"(c[1]), "+f"(c[2]), "+f"(c[3])
        : "r"(a[0]), "r"(a[1]), "r"(a[2]), "r"(a[3]), "r"(b[0]), "r"(b[1]));
}
// fast tanh: 1 - 2/(exp(2x)+1) via ex2/rcp approx (saturates to +-1 at inf)
__device__ __forceinline__ float ftanh(float x) {
    float e;
    asm("ex2.approx.ftz.f32 %0, %1;" : "=f"(e) : "f"(x * 2.885390081777927f));
    float rc;
    asm("rcp.approx.ftz.f32 %0, %1;" : "=f"(rc) : "f"(e + 1.0f));
    return fmaf(-2.0f, rc, 1.0f);
}

// -------- prologue: round+permute embed, Wx, Wo --------------------------
__global__ void prep_k(const float* __restrict__ e, const float* __restrict__ wx,
                       const float* __restrict__ wo) {
    int st = gridDim.x * blockDim.x;
    for (int i = blockIdx.x * blockDim.x + threadIdx.x; i < 1024 * 1024; i += st) {
        int r = i >> 10, k = i & 1023;
        int d = (r << 10) | pig(k);
        g_embr[d] = rndt(e[i]);
        g_Wxr[d]  = rndt(wx[i]);
        g_Wor[d]  = rndt(wo[i]);
    }
}

__global__ void init_k(const float* __restrict__ h0, const float* __restrict__ bx,
                       const float* __restrict__ bh) {
    int i = blockIdx.x * blockDim.x + threadIdx.x;
    if (i < 128) g_flag[i * 32] = 0u;
    if (i < 1024) g_bsum[i] = bx[i] + bh[i];
    for (int j = i; j < Bb * Hh; j += gridDim.x * blockDim.x) {
        int r = j >> 10, k = j & 1023;
        g_h[0][(r << 10) | pig(k)] = rndt(h0[j]);
    }
}

// -------- eproj GEMM: C = A @ W^T + bias (1024x1024) ----------------------
#define PS 44
#define TSZ 5632

__device__ __forceinline__ void stage_p(const float* const* rp, const float* __restrict__ W,
                                        int n0, int k0, float* As, float* Bs, int tid) {
    #pragma unroll
    for (int j = 0; j < 4; j++) {
        int c = j * 256 + tid; int r = c >> 3, o = c & 7;
        cp16(As + r * PS + o * 4, rp[r] + k0 + o * 4);
    }
    #pragma unroll
    for (int j = 0; j < 4; j++) {
        int c = j * 256 + tid; int r = c >> 3, o = c & 7;
        cp16(Bs + r * PS + o * 4, W + (size_t)(n0 + r) * 1024 + k0 + o * 4);
    }
}

__global__ __launch_bounds__(256, 2) void gemm_k(const float* __restrict__ Ab,
                                                 const float* __restrict__ W,
                                                 const float* __restrict__ bias,
                                                 float* __restrict__ C) {
    extern __shared__ float sm[];
    float* As = sm;
    float* Bs = sm + 2 * TSZ;
    const float** rp = (const float**)(sm + 4 * TSZ);

    const int tid = threadIdx.x;
    if (tid < 128) rp[tid] = Ab + ((size_t)blockIdx.y * 128 + tid) * 1024;
    __syncthreads();

    const int n0 = blockIdx.x * 128;
    const int lane = tid & 31, w = tid >> 5;
    const int g = lane >> 2, t4 = lane & 3;
    const int wm = (w >> 2) * 64, wn = (w & 3) * 32;

    float acc[4][4][4];
    #pragma unroll
    for (int a = 0; a < 4; a++)
        #pragma unroll
        for (int b = 0; b < 4; b++)
            #pragma unroll
            for (int c = 0; c < 4; c++) acc[a][b][c] = 0.f;

    stage_p(rp, W, n0, 0, As, Bs, tid);
    cp_commit();

    for (int ks = 0; ks < 32; ks++) {
        cp_wait<0>();
        __syncthreads();
        if (ks < 31) {
            int nb2 = (ks + 1) & 1;
            stage_p(rp, W, n0, (ks + 1) * 32, As + nb2 * TSZ, Bs + nb2 * TSZ, tid);
            cp_commit();
        }
        const float* A_ = As + (ks & 1) * TSZ;
        const float* B_ = Bs + (ks & 1) * TSZ;
        #pragma unroll
        for (int kk = 0; kk < 32; kk += 8) {
            uint32_t a[4][4];
            #pragma unroll
            for (int mi = 0; mi < 4; mi++) {
                float2 p0 = *(const float2*)&A_[(wm + mi * 16 + g) * PS + kk + 2 * t4];
                float2 p1 = *(const float2*)&A_[(wm + mi * 16 + 8 + g) * PS + kk + 2 * t4];
                a[mi][0] = __float_as_uint(p0.x); a[mi][1] = __float_as_uint(p1.x);
                a[mi][2] = __float_as_uint(p0.y); a[mi][3] = __float_as_uint(p1.y);
            }
            #pragma unroll
            for (int ni = 0; ni < 4; ni++) {
                float2 q = *(const float2*)&B_[(wn + ni * 8 + g) * PS + kk + 2 * t4];
                uint32_t b[2] = { __float_as_uint(q.x), __float_as_uint(q.y) };
                #pragma unroll
                for (int mi = 0; mi < 4; mi++)
                    mma8(acc[mi][ni], a[mi], b);
            }
        }
    }

    const int m0 = blockIdx.y * 128;
    #pragma unroll
    for (int ni = 0; ni < 4; ni++) {
        int nc = n0 + wn + ni * 8 + 2 * t4;
        float b0 = bias[nc], b1 = bias[nc + 1];
        #pragma unroll
        for (int mi = 0; mi < 4; mi++) {
            int r0 = m0 + wm + mi * 16 + g;
            *(float2*)&C[(size_t)r0 * 1024 + nc] =
                make_float2(acc[mi][ni][0] + b0, acc[mi][ni][1] + b1);
            *(float2*)&C[(size_t)(r0 + 8) * 1024 + nc] =
                make_float2(acc[mi][ni][2] + b0, acc[mi][ni][3] + b1);
        }
    }
}

// -------- fused recurrence + output kernel (v2) ---------------------------
// 128 CTAs = 4 M-groups x 32 N-CTAs, 256 thr (8 warps).
// Iteration t (0..Tt+1):
//   t>=2 : y(t-2) mma from RESIDENT SB chunks (h(t-2)) with Wo via cp.async
//          ring in Pa areas -> y partials -> PaY.  Runs in the poll window.
//   t<=Tt: poll producers, stage h(t-1) (one-shot 4 chunks)
//   S1; y-reduce + y_e store (hides under stage RT)
//   t<Tt : h-mma -> h partials -> PaH (SB chunks stay live for next y)
//   S2; h epilogue (tanh, hd, release — same position as R15); S3
#define STG 36
#define CHB (32 * STG)              // 1152 floats
#define CHW (4 * CHB)               // 4608 floats per warp staging
#define PAH_O (8 * CHW)             // 36864
#define PAY_O (PAH_O + 8 * CHB)     // 46080
#define SMEM_RF (PAY_O + 8 * CHB)   // 55296 floats = 221184 B

__global__ __launch_bounds__(256, 1) void rnn_k(const float* __restrict__ Wh,
                                                const int* __restrict__ xtok,
                                                const float* __restrict__ bo,
                                                float* __restrict__ h_e,
                                                float* __restrict__ y_e) {
    extern __shared__ float sm[];
    float* Stg = sm;
    float* PaH = sm + PAH_O;
    float* PaY = sm + PAY_O;

    const int tid = threadIdx.x;
    const int nq = blockIdx.x & 31, mq = blockIdx.x >> 5;
    const int nb = nq * 32, mb = mq * 32;

    const int lane = tid & 31, w = tid >> 5;
    const int g = lane >> 2, t4 = lane & 3;
    const int kb = w * 128;
    float* SB = Stg + w * CHW;
    float* PaHw = PaH + w * CHB;
    float* PaYw = PaY + w * CHB;
    const int srow = lane >> 3, su = lane & 7;

    unsigned int* pflag = &g_flag[((mq << 5) | (4 * w + (lane & 3))) * 32];
    unsigned int* myflag = &g_flag[blockIdx.x * 32];

    // Wh B-fragments in registers (rounded RNA; once)
    uint32_t bfr[4][16][2];
    #pragma unroll
    for (int ni = 0; ni < 4; ni++) {
        const float* Wrow = Wh + (size_t)(nb + ni * 8 + g) * 1024 + kb + t4;
        #pragma unroll
        for (int kf = 0; kf < 16; kf++) {
            bfr[ni][kf][0] = f2t(Wrow[kf * 8]);
            bfr[ni][kf][1] = f2t(Wrow[kf * 8 + 4]);
        }
    }
    const float* wosrc = g_Wor + (size_t)nb * 1024 + kb;   // this CTA/warp's Wo slab

    // epilogue mapping (tid<128): row er, cols [gcb, gcb+8)
    const int er = tid & 31, eblk = tid >> 5;
    const int gr = mb + er, gcb = nb + eblk * 8;
    float4 xq0, xq1, bov0, bov1;
    if (tid < 128) {
        int tk = xtok[gr * Tt];
        xq0 = *(const float4*)&g_eproj[(size_t)tk * 1024 + gcb];
        xq1 = *(const float4*)&g_eproj[(size_t)tk * 1024 + gcb + 4];
        bov0 = *(const float4*)&bo[gcb];
        bov1 = *(const float4*)&bo[gcb + 4];
    }
    __syncthreads();

    for (int t = 0; t <= Tt + 1; t++) {
        const bool do_y = (t >= 2);
        const bool do_stage = (t <= Tt);
        const bool do_h = (t < Tt);

        float acc[2][4][4];

        // ==== phase 1: y(t-2) from resident SB chunks ====
        if (do_y) {
            #pragma unroll
            for (int a = 0; a < 2; a++)
                #pragma unroll
                for (int b = 0; b < 4; b++)
                    #pragma unroll
                    for (int c = 0; c < 4; c++) acc[a][b][c] = 0.f;

            // Wo ring: chunk0->PaHw, chunk1->PaYw, then reuse
            #pragma unroll
            for (int j = 0; j < 8; j++) {
                int r = srow + 4 * j;
                cp16(PaHw + r * STG + su * 4, wosrc + (size_t)r * 1024 + su * 4);
            }
            cp_commit();
            #pragma unroll
            for (int j = 0; j < 8; j++) {
                int r = srow + 4 * j;
                cp16(PaYw + r * STG + su * 4, wosrc + (size_t)r * 1024 + 32 + su * 4);
            }
            cp_commit();

            #pragma unroll
            for (int c = 0; c < 4; c++) {
                if (c < 3) cp_wait<1>(); else cp_wait<0>();
                __syncwarp();
                const float* A_ = SB + c * CHB;
                const float* Bw = (c & 1) ? PaYw : PaHw;
                #pragma unroll
                for (int kf = 0; kf < 4; kf++) {
                    uint32_t a[2][4];
                    #pragma unroll
                    for (int mi = 0; mi < 2; mi++) {
                        float2 p0 = *(const float2*)&A_[(mi * 16 + g) * STG + kf * 8 + 2 * t4];
                        float2 p1 = *(const float2*)&A_[(mi * 16 + 8 + g) * STG + kf * 8 + 2 * t4];
                        a[mi][0] = __float_as_uint(p0.x); a[mi][1] = __float_as_uint(p1.x);
                        a[mi][2] = __float_as_uint(p0.y); a[mi][3] = __float_as_uint(p1.y);
                    }
                    #pragma unroll
                    for (int ni = 0; ni < 4; ni++) {
                        float2 q = *(const float2*)&Bw[(ni * 8 + g) * STG + kf * 8 + 2 * t4];
                        uint32_t b[2] = { __float_as_uint(q.x), __float_as_uint(q.y) };
                        mma8(acc[0][ni], a[0], b);
                        mma8(acc[1][ni], a[1], b);
                    }
                }
                if (c < 2) {   // restage Wo chunk c+2 into the buffer just consumed
                    __syncwarp();
                    float* dst = (c & 1) ? PaYw : PaHw;
                    #pragma unroll
                    for (int j = 0; j < 8; j++) {
                        int r = srow + 4 * j;
                        cp16(dst + r * STG + su * 4,
                             wosrc + (size_t)r * 1024 + (c + 2) * 32 + su * 4);
                    }
                    cp_commit();
                }
            }
            // y partials -> PaYw (chunk-3 buffer, consumed; warp-private)
            #pragma unroll
            for (int mi = 0; mi < 2; mi++)
                #pragma unroll
                for (int ni = 0; ni < 4; ni++) {
                    int nc = ni * 8 + 2 * t4;
                    *(float2*)&PaYw[(mi * 16 + g) * STG + nc] =
                        make_float2(acc[mi][ni][0], acc[mi][ni][1]);
                    *(float2*)&PaYw[(mi * 16 + 8 + g) * STG + nc] =
                        make_float2(acc[mi][ni][2], acc[mi][ni][3]);
                }
        }

        // ==== phase 2: poll + one-shot stage of h(t-1) ====
        if (do_stage) {
            const float* gsrc = g_h[t & 1] + (size_t)mb * 1024 + kb;
            if (t > 0 && lane < 4) {
                unsigned tgt = (unsigned)t, vv;
                do {
                    asm volatile("ld.acquire.gpu.u32 %0, [%1];" : "=r"(vv) : "l"(pflag));
                } while (vv < tgt);
            }
            __syncwarp();
            #pragma unroll
            for (int cc = 0; cc < 4; cc++) {
                #pragma unroll
                for (int j = 0; j < 8; j++) {
                    int r = srow + 4 * j;
                    cp16(SB + cc * CHB + r * STG + su * 4,
                         gsrc + (size_t)r * 1024 + cc * 32 + su * 4);
                }
                cp_commit();
            }
        }
        __syncthreads();   // S1: y partials visible; stage in flight

        // ==== y reduce + y_e store (hides under stage round trip) ====
        if (do_y && tid < 128) {
            float s[8] = {0.f,0.f,0.f,0.f,0.f,0.f,0.f,0.f};
            #pragma unroll
            for (int ww = 0; ww < 8; ww++) {
                const float* Rr = PaY + ww * CHB + er * STG + eblk * 8;
                float4 r0 = *(const float4*)&Rr[0];
                float4 r1 = *(const float4*)&Rr[4];
                s[0] += r0.x; s[1] += r0.y; s[2] += r0.z; s[3] += r0.w;
                s[4] += r1.x; s[5] += r1.y; s[6] += r1.z; s[7] += r1.w;
            }
            size_t yrow = ((size_t)gr * Tt + (t - 2)) * 1024 + gcb;
            *(float4*)&y_e[yrow] =
                make_float4(s[0] + bov0.x, s[1] + bov0.y, s[2] + bov0.z, s[3] + bov0.w);
            *(float4*)&y_e[yrow + 4] =
                make_float4(s[4] + bov1.x, s[5] + bov1.y, s[6] + bov1.z, s[7] + bov1.w);
        }

        // ==== phase 3: h-mma ====
        if (do_h) {
            #pragma unroll
            for (int a = 0; a < 2; a++)
                #pragma unroll
                for (int b = 0; b < 4; b++)
                    #pragma unroll
                    for (int c = 0; c < 4; c++) acc[a][b][c] = 0.f;
            #pragma unroll
            for (int c = 0; c < 4; c++) {
                if (c == 0) cp_wait<3>();
                else if (c == 1) cp_wait<2>();
                else if (c == 2) cp_wait<1>();
                else cp_wait<0>();
                __syncwarp();
                const float* B_ = SB + c * CHB;
                #pragma unroll
                for (int kf = 0; kf < 4; kf++) {
                    uint32_t a[2][4];
                    #pragma unroll
                    for (int mi = 0; mi < 2; mi++) {
                        float2 p0 = *(const float2*)&B_[(mi * 16 + g) * STG + kf * 8 + 2 * t4];
                        float2 p1 = *(const float2*)&B_[(mi * 16 + 8 + g) * STG + kf * 8 + 2 * t4];
                        a[mi][0] = __float_as_uint(p0.x); a[mi][1] = __float_as_uint(p1.x);
                        a[mi][2] = __float_as_uint(p0.y); a[mi][3] = __float_as_uint(p1.y);
                    }
                    #pragma unroll
                    for (int ni = 0; ni < 4; ni++) {
                        mma8(acc[0][ni], a[0], bfr[ni][c * 4 + kf]);
                        mma8(acc[1][ni], a[1], bfr[ni][c * 4 + kf]);
                    }
                }
            }
            // h partials -> PaHw (SB chunks stay live for next iteration's y)
            #pragma unroll
            for (int mi = 0; mi < 2; mi++)
                #pragma unroll
                for (int ni = 0; ni < 4; ni++) {
                    int nc = ni * 8 + 2 * t4;
                    *(float2*)&PaHw[(mi * 16 + g) * STG + nc] =
                        make_float2(acc[mi][ni][0], acc[mi][ni][1]);
                    *(float2*)&PaHw[(mi * 16 + 8 + g) * STG + nc] =
                        make_float2(acc[mi][ni][2], acc[mi][ni][3]);
                }
        } else if (do_stage) {
            cp_wait<0>();   // t == Tt: retire stage groups for final y iteration
            __syncwarp();
        }
        __syncthreads();   // S2: h partials visible

        // ==== phase 4: h epilogue (tanh, hd, release) ====
        if (do_h && tid < 128) {
            float* hd = g_h[(t + 1) & 1];
            float s[8] = {0.f,0.f,0.f,0.f,0.f,0.f,0.f,0.f};
            #pragma unroll
            for (int ww = 0; ww < 8; ww++) {
                const float* Rr = PaH + ww * CHB + er * STG + eblk * 8;
                float4 r0 = *(const float4*)&Rr[0];
                float4 r1 = *(const float4*)&Rr[4];
                s[0] += r0.x; s[1] += r0.y; s[2] += r0.z; s[3] += r0.w;
                s[4] += r1.x; s[5] += r1.y; s[6] += r1.z; s[7] += r1.w;
            }
            float v[8], r[8];
            v[0] = ftanh(s[0] + xq0.x); v[1] = ftanh(s[1] + xq0.y);
            v[2] = ftanh(s[2] + xq0.z); v[3] = ftanh(s[3] + xq0.w);
            v[4] = ftanh(s[4] + xq1.x); v[5] = ftanh(s[5] + xq1.y);
            v[6] = ftanh(s[6] + xq1.z); v[7] = ftanh(s[7] + xq1.w);
            #pragma unroll
            for (int j = 0; j < 8; j++) r[j] = rndt(v[j]);
            *(float4*)&hd[(size_t)gr * 1024 + gcb]     = make_float4(r[0], r[4], r[1], r[5]);
            *(float4*)&hd[(size_t)gr * 1024 + gcb + 4] = make_float4(r[2], r[6], r[3], r[7]);

            asm volatile("bar.sync 1, 128;" ::: "memory");
            if (tid == 0)
                asm volatile("red.release.gpu.global.add.u32 [%0], %1;"
                             :: "l"(myflag), "r"(1u) : "memory");

            size_t orow = ((size_t)gr * Tt + t) * 1024 + gcb;
            *(float4*)&h_e[orow]     = make_float4(v[0], v[1], v[2], v[3]);
            *(float4*)&h_e[orow + 4] = make_float4(v[4], v[5], v[6], v[7]);
            if (t + 1 < Tt) {
                int tk = xtok[gr * Tt + t + 1];
                xq0 = *(const float4*)&g_eproj[(size_t)tk * 1024 + gcb];
                xq1 = *(const float4*)&g_eproj[(size_t)tk * 1024 + gcb + 4];
            }
        }
        __syncthreads();   // S3: Pa reads done -> areas reusable next iteration
    }
}

// -------- launch ---------------------------------------------------------
extern "C" void kernel_launch(void* const* d_in, const int* in_sizes, int n_in,
                              void* d_out, int out_size) {
    (void)in_sizes; (void)n_in; (void)out_size;
    const int*   x      = (const int*)d_in[0];
    const float* h_init = (const float*)d_in[1];
    const float* embed  = (const float*)d_in[2];
    const float* Wx     = (const float*)d_in[3];
    const float* bx     = (const float*)d_in[4];
    const float* Wh     = (const float*)d_in[5];
    const float* bh     = (const float*)d_in[6];
    const float* Wo     = (const float*)d_in[7];
    const float* bo     = (const float*)d_in[8];

    float* out = (float*)d_out;
    float* h_e = out;                       // [B][T][H]
    float* y_e = out + (size_t)BT * Hh;     // [B][T][V]

    const int SMEM_P = 4 * TSZ * 4 + 128 * 8;               // 91136
    const int SMEM_R = SMEM_RF * 4;                         // 221184

    cudaFuncSetAttribute(gemm_k, cudaFuncAttributeMaxDynamicSharedMemorySize, SMEM_P);
    cudaFuncSetAttribute(rnn_k,  cudaFuncAttributeMaxDynamicSharedMemorySize, SMEM_R);

    void* ep_ptr = nullptr;   cudaGetSymbolAddress(&ep_ptr, g_eproj);
    void* emb_ptr = nullptr;  cudaGetSymbolAddress(&emb_ptr, g_embr);
    void* wx_ptr = nullptr;   cudaGetSymbolAddress(&wx_ptr, g_Wxr);
    void* bs_ptr = nullptr;   cudaGetSymbolAddress(&bs_ptr, g_bsum);

    // 1. round+permute embed/Wx/Wo; reset flags; bx+bh; h_init -> g_h[0]
    prep_k<<<512, 256>>>(embed, Wx, Wo);
    init_k<<<128, 256>>>(h_init, bx, bh);
    // 2. eproj = embed_r @ Wx_r^T + (bx+bh)   [1024x1024 — gather commutes]
    gemm_k<<<dim3(8, 8), 256, SMEM_P>>>((const float*)emb_ptr,
                                        (const float*)wx_ptr, (const float*)bs_ptr,
                                        (float*)ep_ptr);
    // 3. fused recurrence + output projection -> h_e, y_e
    rnn_k<<<128, 256, SMEM_R>>>(Wh, x, bo, h_e, y_e);
}